// round 5
// baseline (speedup 1.0000x reference)
#include <cuda_runtime.h>

typedef unsigned long long ull;

// ---------------- f32x2 packed math (FFMA2 — PTX-only on sm_103a) ----------
#define FMA2(d,a,b,c) asm("fma.rn.f32x2 %0, %1, %2, %3;" : "=l"(d) : "l"(a), "l"(b), "l"(c))
#define MUL2(d,a,b)   asm("mul.rn.f32x2 %0, %1, %2;"     : "=l"(d) : "l"(a), "l"(b))
#define ADD2(d,a,b)   asm("add.rn.f32x2 %0, %1, %2;"     : "=l"(d) : "l"(a), "l"(b))
#define EX2(d,s)      asm("ex2.approx.f32 %0, %1;"       : "=f"(d) : "f"(s))

__device__ __forceinline__ ull splat2(float f) {
    unsigned u = __float_as_uint(f);
    return ((ull)u << 32) | (ull)u;
}
__device__ __forceinline__ float lo2(ull v) { return __uint_as_float((unsigned)v); }
__device__ __forceinline__ float hi2(ull v) { return __uint_as_float((unsigned)(v >> 32)); }
__device__ __forceinline__ ull pack2(float lo, float hi) {
    return ((ull)__float_as_uint(hi) << 32) | (ull)__float_as_uint(lo);
}

// ---------------- problem constants ----------------------------------------
// B=2, C=256, N=4096, NUM_HEAD=4, D=8, AT_HEAD=64, BH=8
#define NTOK   4096
#define BH_CNT 8
#define NSPLIT 16                // n-range splits
#define NSEG   (NTOK / NSPLIT)   // 256 n per attn CTA

#define LOG2E  1.4426950408889634f

// ---------------- device scratch (no allocation allowed) -------------------
// Two k-half partial buffers from the qkv GEMM (summed during attn staging).
// Q/V: interleaved pair layout [bh][n/2][d*2 + (n&1)]   (q pre-scaled by log2e)
// K  : [bh][n][d]
__device__ float g_Q[BH_CNT * NTOK * 8];
__device__ float g_K[BH_CNT * NTOK * 8];
__device__ float g_V[BH_CNT * NTOK * 8];
__device__ float g_Q2[BH_CNT * NTOK * 8];
__device__ float g_K2[BH_CNT * NTOK * 8];
__device__ float g_V2[BH_CNT * NTOK * 8];
// partials: [bh][split][j in 0..8 (8 num + 1 den)][m]
__device__ float g_P[BH_CNT * NSPLIT * 9 * NTOK];

// ============================================================================
// Kernel 1: fused QKV projection, register-tiled GEMM with f32x2 row-pairs.
// C[96 x 8192] = W[96 x 256] @ X[256 x 8192], split 2-ways over k.
// 256 blocks = b(2) x ntile(64) x khalf(2). 256 threads:
//   rg = warp id -> 12 rows (6 row-pairs), ng -> 2 n.
// Per scalar k: 3 broadcast LDS.128 (W row-pairs) + 1 LDS.64 (x) + 12 FFMA2.
// ============================================================================
#define WPAD 100   // W smem row stride (floats): mult of 4, bank-spread

__global__ void __launch_bounds__(256) qkv_kernel(
    const float* __restrict__ x,
    const float* __restrict__ Wq, const float* __restrict__ bq,
    const float* __restrict__ Wk, const float* __restrict__ bk,
    const float* __restrict__ Wv, const float* __restrict__ bv)
{
    __shared__ __align__(16) float xs[64 * 64];     // [k_local][n]  16 KB
    __shared__ __align__(16) float ws[64 * WPAD];   // [k_local][r]  25.6 KB

    const int b     = blockIdx.x >> 7;          // 256 blocks
    const int khalf = (blockIdx.x >> 6) & 1;
    const int n0    = (blockIdx.x & 63) * 64;
    const int tid   = threadIdx.x;
    const int rg    = tid >> 5;                 // 0..7, constant per warp
    const int ng    = tid & 31;                 // 2 n each

    ull acc2[6][2];                              // [row-pair][n]
#pragma unroll
    for (int pr = 0; pr < 6; ++pr) { acc2[pr][0] = 0ull; acc2[pr][1] = 0ull; }

    for (int kc = 0; kc < 2; ++kc) {
        const int kb = khalf * 128 + kc * 64;    // absolute k base
        __syncthreads();
        // stage x chunk: x[b][kb + c][n0..n0+63]  (1024 float4)
#pragma unroll
        for (int t = 0; t < 4; ++t) {
            int idx = tid + t * 256;
            int c   = idx >> 4;
            int nq  = idx & 15;
            float4 xv = __ldg((const float4*)(x + (b * 256 + kb + c) * NTOK + n0) + nq);
            *(float4*)&xs[c * 64 + nq * 4] = xv;
        }
        // stage W chunk: ws[k][r] = W[r][kb + k]
#pragma unroll
        for (int t = 0; t < 6; ++t) {
            int idx = tid + t * 256;
            int r   = idx >> 4;
            int k4  = idx & 15;
            const float* base = (r < 32) ? Wq : ((r < 64) ? Wk : Wv);
            float4 w = __ldg((const float4*)(base + (r & 31) * 256 + kb) + k4);
            ws[(k4 * 4 + 0) * WPAD + r] = w.x;
            ws[(k4 * 4 + 1) * WPAD + r] = w.y;
            ws[(k4 * 4 + 2) * WPAD + r] = w.z;
            ws[(k4 * 4 + 3) * WPAD + r] = w.w;
        }
        __syncthreads();

#pragma unroll 8
        for (int k = 0; k < 64; ++k) {
            float2 xv = *(const float2*)&xs[k * 64 + ng * 2];
            ull x0 = splat2(xv.x);
            ull x1 = splat2(xv.y);
            const ulonglong2* wr = (const ulonglong2*)&ws[k * WPAD + rg * 12];
            ulonglong2 wa = wr[0], wb = wr[1], wc = wr[2];
            ull w01 = wa.x, w23 = wa.y, w45 = wb.x, w67 = wb.y, w89 = wc.x, wAB = wc.y;
            FMA2(acc2[0][0], w01, x0, acc2[0][0]); FMA2(acc2[0][1], w01, x1, acc2[0][1]);
            FMA2(acc2[1][0], w23, x0, acc2[1][0]); FMA2(acc2[1][1], w23, x1, acc2[1][1]);
            FMA2(acc2[2][0], w45, x0, acc2[2][0]); FMA2(acc2[2][1], w45, x1, acc2[2][1]);
            FMA2(acc2[3][0], w67, x0, acc2[3][0]); FMA2(acc2[3][1], w67, x1, acc2[3][1]);
            FMA2(acc2[4][0], w89, x0, acc2[4][0]); FMA2(acc2[4][1], w89, x1, acc2[4][1]);
            FMA2(acc2[5][0], wAB, x0, acc2[5][0]); FMA2(acc2[5][1], wAB, x1, acc2[5][1]);
        }
    }

    // write out with bias (khalf 0 only), into attention-friendly layouts
    float* Qo = khalf ? g_Q2 : g_Q;
    float* Ko = khalf ? g_K2 : g_K;
    float* Vo = khalf ? g_V2 : g_V;
#pragma unroll
    for (int pr = 0; pr < 6; ++pr) {
#pragma unroll
        for (int sub = 0; sub < 2; ++sub) {
            int r = rg * 12 + pr * 2 + sub;
            int p = r >> 5;          // 0=q,1=k,2=v
            int h = (r >> 3) & 3;
            int d = r & 7;
            const float* bias = (p == 0) ? bq : ((p == 1) ? bk : bv);
            float bval = khalf ? 0.0f : __ldg(&bias[h * 8 + d]);
            int bh = b * 4 + h;
#pragma unroll
            for (int c = 0; c < 2; ++c) {
                int n = n0 + ng * 2 + c;
                float val = (sub ? hi2(acc2[pr][c]) : lo2(acc2[pr][c])) + bval;
                if (p == 0) {
                    Qo[bh * (NTOK * 8) + (n >> 1) * 16 + d * 2 + (n & 1)] = LOG2E * val;
                } else if (p == 1) {
                    Ko[bh * (NTOK * 8) + n * 8 + d] = val;
                } else {
                    Vo[bh * (NTOK * 8) + (n >> 1) * 16 + d * 2 + (n & 1)] = val;
                }
            }
        }
    }
}

// ============================================================================
// Kernel 2: fused attention core (4 m-cols/thread), exp via ex2 (MUFU).
// Grid: x = (m-tile 0..3) | (split 0..15)<<2 ; y = bh.  512 CTAs, 16KB smem.
// Staging sums the two qkv k-half partial buffers.
// ============================================================================
__global__ void __launch_bounds__(256) attn_kernel()
{
    __shared__ __align__(16) float sq[NSEG * 8];   // 8 KB
    __shared__ __align__(16) float sv[NSEG * 8];   // 8 KB

    const int bh  = blockIdx.y;
    const int mt  = blockIdx.x & 3;
    const int sp  = blockIdx.x >> 2;
    const int tid = threadIdx.x;

    const float4* Qa = (const float4*)(g_Q  + bh * (NTOK * 8) + sp * (NSEG * 8));
    const float4* Qb = (const float4*)(g_Q2 + bh * (NTOK * 8) + sp * (NSEG * 8));
    const float4* Va = (const float4*)(g_V  + bh * (NTOK * 8) + sp * (NSEG * 8));
    const float4* Vb = (const float4*)(g_V2 + bh * (NTOK * 8) + sp * (NSEG * 8));
#pragma unroll
    for (int i = tid; i < NSEG * 8 / 4; i += 256) {
        float4 qa = Qa[i], qb = Qb[i];
        float4 va = Va[i], vb = Vb[i];
        ((float4*)sq)[i] = make_float4(qa.x + qb.x, qa.y + qb.y, qa.z + qb.z, qa.w + qb.w);
        ((float4*)sv)[i] = make_float4(va.x + vb.x, va.y + vb.y, va.z + vb.z, va.w + vb.w);
    }

    // k for this thread's 4 m-columns (sum of halves), splatted into f32x2
    ull k2[4][8];
#pragma unroll
    for (int j = 0; j < 4; ++j) {
        int m = mt * 1024 + tid + j * 256;
        const float4* kp  = (const float4*)(g_K  + bh * (NTOK * 8) + m * 8);
        const float4* kp2 = (const float4*)(g_K2 + bh * (NTOK * 8) + m * 8);
        float4 ka = __ldg(kp),  kb = __ldg(kp + 1);
        float4 kc = __ldg(kp2), kd = __ldg(kp2 + 1);
        k2[j][0] = splat2(ka.x + kc.x); k2[j][1] = splat2(ka.y + kc.y);
        k2[j][2] = splat2(ka.z + kc.z); k2[j][3] = splat2(ka.w + kc.w);
        k2[j][4] = splat2(kb.x + kd.x); k2[j][5] = splat2(kb.y + kd.y);
        k2[j][6] = splat2(kb.z + kd.z); k2[j][7] = splat2(kb.w + kd.w);
    }

    ull num2[4][8], den2[4];
#pragma unroll
    for (int j = 0; j < 4; ++j) {
        den2[j] = 0ull;
#pragma unroll
        for (int d = 0; d < 8; ++d) num2[j][d] = 0ull;
    }

    __syncthreads();

#pragma unroll 2
    for (int p = 0; p < NSEG / 2; ++p) {
        const ulonglong2* qp = (const ulonglong2*)sq + p * 4;
        ull q2[8];
        {
            ulonglong2 t0 = qp[0], t1 = qp[1], t2 = qp[2], t3 = qp[3];
            q2[0] = t0.x; q2[1] = t0.y; q2[2] = t1.x; q2[3] = t1.y;
            q2[4] = t2.x; q2[5] = t2.y; q2[6] = t3.x; q2[7] = t3.y;
        }

        ull s2[4];
#pragma unroll
        for (int j = 0; j < 4; ++j) {
            MUL2(s2[j], q2[0], k2[j][0]);
#pragma unroll
            for (int d = 1; d < 8; ++d) FMA2(s2[j], q2[d], k2[j][d], s2[j]);
        }

        ull e2[4];
#pragma unroll
        for (int j = 0; j < 4; ++j) {
            float el, eh;
            EX2(el, lo2(s2[j]));
            EX2(eh, hi2(s2[j]));
            e2[j] = pack2(el, eh);
            ADD2(den2[j], den2[j], e2[j]);
        }

        const ulonglong2* vp = (const ulonglong2*)sv + p * 4;
        ull v2[8];
        {
            ulonglong2 t0 = vp[0], t1 = vp[1], t2 = vp[2], t3 = vp[3];
            v2[0] = t0.x; v2[1] = t0.y; v2[2] = t1.x; v2[3] = t1.y;
            v2[4] = t2.x; v2[5] = t2.y; v2[6] = t3.x; v2[7] = t3.y;
        }
#pragma unroll
        for (int d = 0; d < 8; ++d)
#pragma unroll
            for (int j = 0; j < 4; ++j)
                FMA2(num2[j][d], e2[j], v2[d], num2[j][d]);
    }

#pragma unroll
    for (int j = 0; j < 4; ++j) {
        int m = mt * 1024 + tid + j * 256;
        int base = ((bh * NSPLIT + sp) * 9) * NTOK + m;
#pragma unroll
        for (int d = 0; d < 8; ++d)
            g_P[base + d * NTOK] = lo2(num2[j][d]) + hi2(num2[j][d]);
        g_P[base + 8 * NTOK] = lo2(den2[j]) + hi2(den2[j]);
    }
}

// ============================================================================
// Kernel 3: reduce splits, normalize, Wo projection, gamma, residual.
// Thread per (bh, m, e-half): 65536 threads, each produces 32 outputs.
// ============================================================================
__global__ void __launch_bounds__(256) out_kernel(
    const float* __restrict__ x,
    const float* __restrict__ Wo, const float* __restrict__ bo,
    const float* __restrict__ gamma,
    float* __restrict__ out)
{
    __shared__ float wo_s[256];   // 32 e x 8 d
    __shared__ float bo_s[32];
    __shared__ float gam_s;

    const int t  = blockIdx.x * 256 + threadIdx.x;
    const int m  = t & 4095;
    const int bh = (t >> 12) & 7;
    const int eh = t >> 15;       // e-half 0/1 (uniform per block)
    const int b  = bh >> 2;
    const int h  = bh & 3;

    wo_s[threadIdx.x] = Wo[h * 512 + eh * 256 + threadIdx.x];
    if (threadIdx.x < 32) bo_s[threadIdx.x] = bo[h * 64 + eh * 32 + threadIdx.x];
    if (threadIdx.x == 0) gam_s = gamma[h];
    __syncthreads();

    float num[8];
#pragma unroll
    for (int d = 0; d < 8; ++d) num[d] = 0.0f;
    float den = 0.0f;

#pragma unroll
    for (int s = 0; s < NSPLIT; ++s) {
        const float* P = g_P + ((bh * NSPLIT + s) * 9) * NTOK + m;
#pragma unroll
        for (int d = 0; d < 8; ++d) num[d] += P[d * NTOK];
        den += P[8 * NTOK];
    }

    const float rden = 1.0f / den;
    float o[8];
#pragma unroll
    for (int d = 0; d < 8; ++d) o[d] = num[d] * rden;

    const float gam = gam_s;
#pragma unroll 4
    for (int e = 0; e < 32; ++e) {
        float y = bo_s[e];
#pragma unroll
        for (int d = 0; d < 8; ++d) y += wo_s[e * 8 + d] * o[d];
        int idx = b * (256 * NTOK) + (h * 64 + eh * 32 + e) * NTOK + m;
        out[idx] = gam * y + x[idx];
    }
}

// ============================================================================
extern "C" void kernel_launch(void* const* d_in, const int* in_sizes, int n_in,
                              void* d_out, int out_size)
{
    const float* x     = (const float*)d_in[0];
    const float* Wq    = (const float*)d_in[1];
    const float* bq    = (const float*)d_in[2];
    const float* Wk    = (const float*)d_in[3];
    const float* bk    = (const float*)d_in[4];
    const float* Wv    = (const float*)d_in[5];
    const float* bv    = (const float*)d_in[6];
    const float* Wo    = (const float*)d_in[7];
    const float* bo    = (const float*)d_in[8];
    const float* gamma = (const float*)d_in[9];
    float* out = (float*)d_out;

    qkv_kernel<<<256, 256>>>(x, Wq, bq, Wk, bk, Wv, bv);
    attn_kernel<<<dim3(4 * NSPLIT, 8), 256>>>();
    out_kernel<<<256, 256>>>(x, Wo, bo, gamma, out);
}